// round 1
// baseline (speedup 1.0000x reference)
#include <cuda_runtime.h>

// BoundaryBCELoss: 5x clamped plus-dilation of two masks + BCE vs target, mean-reduced.
// Strategy: one fused kernel. 64x64 inner tile + halo-5 (74x74) staged in SMEM as
// float2 {hand, object}; 5 in-SMEM dilation iterations with ping-pong buffers and a
// vertical register chain (3 LDS + 1 STS per pixel-iter); BCE with a branch that
// skips MUFU logs on the dominant p==1 fast path; block-reduce + atomicAdd.

#define H_IMG 384
#define W_IMG 384
#define N_IMG 64
#define TILE 64
#define HALO 5
#define LDIM (TILE + 2 * HALO)   // 74
#define NTHREADS 256

__global__ void zero_out_kernel(float* out) { *out = 0.0f; }

__global__ __launch_bounds__(NTHREADS) void boundary_bce_fused_kernel(
    const float* __restrict__ hand,
    const float* __restrict__ obj,
    const float* __restrict__ target,
    float* __restrict__ out)
{
    extern __shared__ float2 smem[];
    float2* buf0 = smem;                 // LDIM*LDIM
    float2* buf1 = smem + LDIM * LDIM;   // LDIM*LDIM

    const int n  = blockIdx.z;
    const int y0 = blockIdx.y * TILE - HALO;
    const int x0 = blockIdx.x * TILE - HALO;
    const int tid = threadIdx.x;

    const size_t img_off = (size_t)n * H_IMG * W_IMG;
    const float* hbase = hand + img_off;
    const float* obase = obj + img_off;

    // ---- Stage halo tile (zero-padded at image borders) ----
    for (int idx = tid; idx < LDIM * LDIM; idx += NTHREADS) {
        int r = idx / LDIM;
        int c = idx - r * LDIM;
        int gr = y0 + r;
        int gc = x0 + c;
        float2 v = make_float2(0.0f, 0.0f);
        if ((unsigned)gr < H_IMG && (unsigned)gc < W_IMG) {
            int g = gr * W_IMG + gc;
            v.x = __ldg(hbase + g);
            v.y = __ldg(obase + g);
        }
        buf0[idx] = v;
    }
    __syncthreads();

    const int tx = tid & 63;
    const int ty = tid >> 6;

    // ---- 5 dilation iterations, valid region shrinks by 1 each side per iter ----
    #pragma unroll
    for (int k = 1; k <= HALO; k++) {
        float2* src = (k & 1) ? buf0 : buf1;
        float2* dst = (k & 1) ? buf1 : buf0;
        const int lo = k;
        const int hi = LDIM - k;
        const int height = hi - lo;
        const int chunk = (height + 3) >> 2;   // 4 row-groups (ty)
        const int r0 = lo + ty * chunk;
        const int r1 = min(r0 + chunk, hi);

        for (int c = lo + tx; c < hi; c += 64) {
            if (r0 < r1) {
                // vertical register chain: carry up & mid, load only the new row below
                float2 up  = src[(r0 - 1) * LDIM + c];
                float2 mid = src[r0 * LDIM + c];
                for (int r = r0; r < r1; r++) {
                    float2 dn = src[(r + 1) * LDIM + c];
                    float2 lf = src[r * LDIM + c - 1];
                    float2 rt = src[r * LDIM + c + 1];
                    float sx = mid.x + up.x + dn.x + lf.x + rt.x;
                    float sy = mid.y + up.y + dn.y + lf.y + rt.y;
                    dst[r * LDIM + c] = make_float2(fminf(sx, 1.0f), fminf(sy, 1.0f));
                    up = mid;
                    mid = dn;
                }
            }
        }
        __syncthreads();
    }

    // ---- BCE over the inner 64x64 region (final dilation result lives in buf1) ----
    const float* tbase = target + img_off;
    float lsum = 0.0f;

    for (int r = HALO + ty; r < HALO + TILE; r += 4) {
        const int c = HALO + tx;   // TILE == 64 == x-thread count
        float2 v = buf1[r * LDIM + c];
        float p = v.x * v.y;
        int gr = y0 + r;
        int gc = x0 + c;
        float t = __ldg(tbase + gr * W_IMG + gc);
        float contrib;
        if (p >= 1.0f) {
            // log(p)=0, max(log(1-p),-100) = -100  -> skip MUFU entirely
            contrib = -100.0f * (1.0f - t);
        } else {
            float lp  = fmaxf(logf(p), -100.0f);        // logf(0) = -inf -> clamped
            float l1p = fmaxf(logf(1.0f - p), -100.0f);
            contrib = t * lp + (1.0f - t) * l1p;
        }
        lsum += contrib;
    }

    // ---- Block reduction ----
    #pragma unroll
    for (int off = 16; off > 0; off >>= 1)
        lsum += __shfl_down_sync(0xffffffffu, lsum, off);

    __syncthreads();                 // done reading buf1; safe to reuse smem
    float* red = (float*)smem;
    if ((tid & 31) == 0) red[tid >> 5] = lsum;
    __syncthreads();

    if (tid < 8) {
        float v = red[tid];
        #pragma unroll
        for (int off = 4; off > 0; off >>= 1)
            v += __shfl_down_sync(0xffu, v, off);
        if (tid == 0) {
            const float inv_total = 1.0f / ((float)N_IMG * H_IMG * W_IMG);
            atomicAdd(out, -v * inv_total);
        }
    }
}

extern "C" void kernel_launch(void* const* d_in, const int* in_sizes, int n_in,
                              void* d_out, int out_size)
{
    const float* hand   = (const float*)d_in[0];
    const float* obj    = (const float*)d_in[1];
    const float* target = (const float*)d_in[2];
    float* out = (float*)d_out;

    const size_t smem_bytes = 2u * LDIM * LDIM * sizeof(float2);  // 87,616 B
    cudaFuncSetAttribute(boundary_bce_fused_kernel,
                         cudaFuncAttributeMaxDynamicSharedMemorySize,
                         (int)smem_bytes);

    zero_out_kernel<<<1, 1>>>(out);

    dim3 grid(W_IMG / TILE, H_IMG / TILE, N_IMG);  // 6 x 6 x 64 = 2304 blocks
    boundary_bce_fused_kernel<<<grid, NTHREADS, smem_bytes>>>(hand, obj, target, out);
}

// round 2
// speedup vs baseline: 1.4452x; 1.4452x over previous
#include <cuda_runtime.h>

// BoundaryBCELoss: 5x clamped plus-dilation of two masks + BCE vs target, mean-reduced.
// Round 2: occupancy fix. TILE 32, LDIM 42, smem 28.2 KB/CTA -> 8 CTAs/SM (was 2).
// float2 {hand,object} packing, ping-pong SMEM buffers, vertical register chain
// (3 LDS.64 + 1 STS.64 per pixel-iter). Out-of-image cells re-zeroed every store to
// exactly match the reference's per-iteration zero padding. BCE fast path skips MUFU
// logs when p==1 (dominant case after 5 clamped dilations of U(0,1) inputs).

#define H_IMG 384
#define W_IMG 384
#define N_IMG 64
#define TILE 32
#define HALO 5
#define LDIM (TILE + 2 * HALO)   // 42
#define NTHREADS 256

__global__ void zero_out_kernel(float* out) { *out = 0.0f; }

__global__ __launch_bounds__(NTHREADS, 8) void boundary_bce_fused_kernel(
    const float* __restrict__ hand,
    const float* __restrict__ obj,
    const float* __restrict__ target,
    float* __restrict__ out)
{
    extern __shared__ float2 smem[];
    float2* buf0 = smem;                 // LDIM*LDIM
    float2* buf1 = smem + LDIM * LDIM;   // LDIM*LDIM

    const int n  = blockIdx.z;
    const int y0 = blockIdx.y * TILE - HALO;
    const int x0 = blockIdx.x * TILE - HALO;
    const int tid = threadIdx.x;

    const size_t img_off = (size_t)n * H_IMG * W_IMG;
    const float* hbase = hand + img_off;
    const float* obase = obj + img_off;

    // ---- Stage halo tile (zero-padded outside the image) ----
    for (int idx = tid; idx < LDIM * LDIM; idx += NTHREADS) {
        int r = idx / LDIM;
        int c = idx - r * LDIM;
        int gr = y0 + r;
        int gc = x0 + c;
        float2 v = make_float2(0.0f, 0.0f);
        if ((unsigned)gr < H_IMG && (unsigned)gc < W_IMG) {
            int g = gr * W_IMG + gc;
            v.x = __ldg(hbase + g);
            v.y = __ldg(obase + g);
        }
        buf0[idx] = v;
    }
    __syncthreads();

    const int tx = tid & 31;   // column lane
    const int ty = tid >> 5;   // 8 row groups

    // ---- 5 dilation iterations; valid region shrinks by 1/side per iteration ----
    #pragma unroll
    for (int k = 1; k <= HALO; k++) {
        float2* src = (k & 1) ? buf0 : buf1;
        float2* dst = (k & 1) ? buf1 : buf0;
        const int lo = k;
        const int hi = LDIM - k;
        const int height = hi - lo;
        const int chunk = (height + 7) >> 3;       // rows per ty-group
        const int r0 = lo + ty * chunk;
        const int r1 = min(r0 + chunk, hi);

        for (int c = lo + tx; c < hi; c += 32) {
            const bool col_in = (unsigned)(x0 + c) < W_IMG;
            if (r0 < r1) {
                // vertical register chain: carry up & mid, load only the new row below
                float2 up  = src[(r0 - 1) * LDIM + c];
                float2 mid = src[r0 * LDIM + c];
                for (int r = r0; r < r1; r++) {
                    float2 dn = src[(r + 1) * LDIM + c];
                    float2 lf = src[r * LDIM + c - 1];
                    float2 rt = src[r * LDIM + c + 1];
                    float sx = fminf(mid.x + up.x + dn.x + lf.x + rt.x, 1.0f);
                    float sy = fminf(mid.y + up.y + dn.y + lf.y + rt.y, 1.0f);
                    // Re-zero out-of-image cells: match reference's per-conv zero pad.
                    const bool in_img = col_in && ((unsigned)(y0 + r) < H_IMG);
                    dst[r * LDIM + c] = in_img ? make_float2(sx, sy)
                                               : make_float2(0.0f, 0.0f);
                    up = mid;
                    mid = dn;
                }
            }
        }
        __syncthreads();
    }

    // ---- BCE over the inner 32x32 region (final result in buf1 after k=5) ----
    const float* tbase = target + img_off;
    float lsum = 0.0f;

    #pragma unroll
    for (int i = tid; i < TILE * TILE; i += NTHREADS) {
        const int r = HALO + (i >> 5);
        const int c = HALO + (i & 31);
        float2 v = buf1[r * LDIM + c];
        float p = v.x * v.y;
        float t = __ldg(tbase + (y0 + r) * W_IMG + (x0 + c));
        float contrib;
        if (p >= 1.0f) {
            // log(p)=0; max(log(1-p), -100) = -100  -> no MUFU
            contrib = -100.0f * (1.0f - t);
        } else {
            float lp  = fmaxf(logf(p), -100.0f);         // logf(0) = -inf -> clamped
            float l1p = fmaxf(logf(1.0f - p), -100.0f);
            contrib = t * lp + (1.0f - t) * l1p;
        }
        lsum += contrib;
    }

    // ---- Block reduction ----
    #pragma unroll
    for (int off = 16; off > 0; off >>= 1)
        lsum += __shfl_down_sync(0xffffffffu, lsum, off);

    __syncthreads();                 // done reading buf1; safe to reuse smem
    float* red = (float*)smem;
    if ((tid & 31) == 0) red[tid >> 5] = lsum;
    __syncthreads();

    if (tid < 8) {
        float v = red[tid];
        #pragma unroll
        for (int off = 4; off > 0; off >>= 1)
            v += __shfl_down_sync(0xffu, v, off);
        if (tid == 0) {
            const float inv_total = 1.0f / ((float)N_IMG * H_IMG * W_IMG);
            atomicAdd(out, -v * inv_total);
        }
    }
}

extern "C" void kernel_launch(void* const* d_in, const int* in_sizes, int n_in,
                              void* d_out, int out_size)
{
    const float* hand   = (const float*)d_in[0];
    const float* obj    = (const float*)d_in[1];
    const float* target = (const float*)d_in[2];
    float* out = (float*)d_out;

    const size_t smem_bytes = 2u * LDIM * LDIM * sizeof(float2);  // 28,224 B
    cudaFuncSetAttribute(boundary_bce_fused_kernel,
                         cudaFuncAttributeMaxDynamicSharedMemorySize,
                         (int)smem_bytes);

    zero_out_kernel<<<1, 1>>>(out);

    dim3 grid(W_IMG / TILE, H_IMG / TILE, N_IMG);  // 12 x 12 x 64 = 9216 blocks
    boundary_bce_fused_kernel<<<grid, NTHREADS, smem_bytes>>>(hand, obj, target, out);
}

// round 3
// speedup vs baseline: 1.4764x; 1.0216x over previous
#include <cuda_runtime.h>

// BoundaryBCELoss: 5x clamped plus-dilation of two masks + BCE vs target, mean-reduced.
// Round 3: issue-bound -> cut instructions/pixel. Column-pair processing (float4 =
// 2 x float2{h,o}), packed add.rn.f32x2 (7 packed adds / 2 px via shared mid-term),
// compile-time per-iteration work mapping (no runtime div), interior-block
// specialization (no boundary predicates for 100/144 blocks).

#define H_IMG 384
#define W_IMG 384
#define N_IMG 64
#define TILE 32
#define HALO 5
#define LDIM (TILE + 2 * HALO)   // 42 (even -> column-pair alignment works)
#define NTHREADS 256

#define ADD_F32X2(out, a, b) \
    asm("add.rn.f32x2 %0, %1, %2;" : "=l"(out) : "l"(a), "l"(b))
#define UNPACK_F32X2(lo, hi, in) \
    asm("mov.b64 {%0, %1}, %2;" : "=f"(lo), "=f"(hi) : "l"(in))

typedef unsigned long long u64;

__global__ void zero_out_kernel(float* out) { *out = 0.0f; }

// One dilation iteration over the shrinking valid region [K, LDIM-K) x [K, LDIM-K).
// Threads own column PAIRS (c even). Pairs may overhang the valid region by one
// column on each side (c = LO-1 when LO odd, c+1 = HI); those extra cells are
// written with garbage but are provably never read by later iterations (reads
// shrink in lockstep), and all SMEM indices stay within [0, LDIM*LDIM).
template <int K, bool INTERIOR>
__device__ __forceinline__ void dilate_iter(const float2* __restrict__ src,
                                            float2* __restrict__ dst,
                                            int tid, int x0, int y0)
{
    constexpr int LO = K;
    constexpr int HI = LDIM - K;
    constexpr int START = LO & ~1;                    // even pair start
    constexpr int NP = (HI - START + 1) >> 1;         // pairs: 21,19,19,17,17
    constexpr int NG = NTHREADS / NP;                 // row groups: 12,13,13,15,15
    constexpr int CH = (HI - LO + NG - 1) / NG;       // rows/group: 4,3,3,3,3

    const int pl  = tid % NP;                          // constant divisor -> mul/shift
    const int grp = tid / NP;
    if (grp >= NG) return;

    const int c  = START + 2 * pl;
    const int r0 = LO + grp * CH;
    const int r1 = min(r0 + CH, HI);
    if (r0 >= r1) return;

    // Vertical register chain: carry up/mid pair-rows, load only the new row below.
    ulonglong2 up  = *(const ulonglong2*)(src + (r0 - 1) * LDIM + c);
    ulonglong2 mid = *(const ulonglong2*)(src + r0 * LDIM + c);

    #pragma unroll
    for (int i = 0; i < CH; i++) {
        const int r = r0 + i;
        if (r >= r1) break;
        ulonglong2 dn = *(const ulonglong2*)(src + (r + 1) * LDIM + c);
        u64 lf = *(const u64*)(src + r * LDIM + (c - 1));
        u64 rt = *(const u64*)(src + r * LDIM + (c + 2));

        // s(c)   = lf + mid.x + mid.y + up.x + dn.x
        // s(c+1) = mid.x + mid.y + rt + up.y + dn.y   (t = mid.x + mid.y shared)
        u64 t, s0, s1;
        ADD_F32X2(t, mid.x, mid.y);
        ADD_F32X2(s0, t, lf);
        ADD_F32X2(s0, s0, up.x);
        ADD_F32X2(s0, s0, dn.x);
        ADD_F32X2(s1, t, rt);
        ADD_F32X2(s1, s1, up.y);
        ADD_F32X2(s1, s1, dn.y);

        float a0, a1, b0, b1;
        UNPACK_F32X2(a0, a1, s0);
        UNPACK_F32X2(b0, b1, s1);
        a0 = fminf(a0, 1.0f); a1 = fminf(a1, 1.0f);
        b0 = fminf(b0, 1.0f); b1 = fminf(b1, 1.0f);

        if (!INTERIOR) {
            // Re-zero out-of-image cells: match reference's per-conv zero padding.
            const bool rin = (unsigned)(y0 + r) < H_IMG;
            if (!(rin && (unsigned)(x0 + c)     < W_IMG)) { a0 = 0.0f; a1 = 0.0f; }
            if (!(rin && (unsigned)(x0 + c + 1) < W_IMG)) { b0 = 0.0f; b1 = 0.0f; }
        }

        *(float4*)(dst + r * LDIM + c) = make_float4(a0, a1, b0, b1);
        up = mid;
        mid = dn;
    }
}

template <bool INTERIOR>
__device__ __forceinline__ void dilate_all(float2* buf0, float2* buf1,
                                           int tid, int x0, int y0)
{
    dilate_iter<1, INTERIOR>(buf0, buf1, tid, x0, y0); __syncthreads();
    dilate_iter<2, INTERIOR>(buf1, buf0, tid, x0, y0); __syncthreads();
    dilate_iter<3, INTERIOR>(buf0, buf1, tid, x0, y0); __syncthreads();
    dilate_iter<4, INTERIOR>(buf1, buf0, tid, x0, y0); __syncthreads();
    dilate_iter<5, INTERIOR>(buf0, buf1, tid, x0, y0); __syncthreads();
}

__global__ __launch_bounds__(NTHREADS, 6) void boundary_bce_fused_kernel(
    const float* __restrict__ hand,
    const float* __restrict__ obj,
    const float* __restrict__ target,
    float* __restrict__ out)
{
    extern __shared__ float2 smem[];
    float2* buf0 = smem;                 // LDIM*LDIM
    float2* buf1 = smem + LDIM * LDIM;   // LDIM*LDIM

    const int n  = blockIdx.z;
    const int y0 = blockIdx.y * TILE - HALO;
    const int x0 = blockIdx.x * TILE - HALO;
    const int tid = threadIdx.x;

    const size_t img_off = (size_t)n * H_IMG * W_IMG;
    const float* hbase = hand + img_off;
    const float* obase = obj + img_off;

    // ---- Stage halo tile (zero-padded outside the image) ----
    for (int idx = tid; idx < LDIM * LDIM; idx += NTHREADS) {
        int r = idx / LDIM;
        int c = idx - r * LDIM;
        int gr = y0 + r;
        int gc = x0 + c;
        float2 v = make_float2(0.0f, 0.0f);
        if ((unsigned)gr < H_IMG && (unsigned)gc < W_IMG) {
            int g = gr * W_IMG + gc;
            v.x = __ldg(hbase + g);
            v.y = __ldg(obase + g);
        }
        buf0[idx] = v;
    }
    __syncthreads();

    const bool interior = (x0 >= 0) && (y0 >= 0) &&
                          (x0 + LDIM <= W_IMG) && (y0 + LDIM <= H_IMG);
    if (interior) dilate_all<true>(buf0, buf1, tid, x0, y0);
    else          dilate_all<false>(buf0, buf1, tid, x0, y0);

    // ---- BCE over the inner 32x32 region (final result in buf1) ----
    const float* tbase = target + img_off;
    float lsum = 0.0f;

    #pragma unroll
    for (int i = tid; i < TILE * TILE; i += NTHREADS) {
        const int r = HALO + (i >> 5);
        const int c = HALO + (i & 31);
        float2 v = buf1[r * LDIM + c];
        float p = v.x * v.y;
        float t = __ldg(tbase + (y0 + r) * W_IMG + (x0 + c));
        float contrib;
        if (p >= 1.0f) {
            // log(p)=0; max(log(1-p), -100) = -100  -> no MUFU
            contrib = -100.0f * (1.0f - t);
        } else {
            float lp  = fmaxf(logf(p), -100.0f);         // logf(0) = -inf -> clamped
            float l1p = fmaxf(logf(1.0f - p), -100.0f);
            contrib = t * lp + (1.0f - t) * l1p;
        }
        lsum += contrib;
    }

    // ---- Block reduction ----
    #pragma unroll
    for (int off = 16; off > 0; off >>= 1)
        lsum += __shfl_down_sync(0xffffffffu, lsum, off);

    __syncthreads();                 // done reading buf1; safe to reuse smem
    float* red = (float*)smem;
    if ((tid & 31) == 0) red[tid >> 5] = lsum;
    __syncthreads();

    if (tid < 8) {
        float v = red[tid];
        #pragma unroll
        for (int off = 4; off > 0; off >>= 1)
            v += __shfl_down_sync(0xffu, v, off);
        if (tid == 0) {
            const float inv_total = 1.0f / ((float)N_IMG * H_IMG * W_IMG);
            atomicAdd(out, -v * inv_total);
        }
    }
}

extern "C" void kernel_launch(void* const* d_in, const int* in_sizes, int n_in,
                              void* d_out, int out_size)
{
    const float* hand   = (const float*)d_in[0];
    const float* obj    = (const float*)d_in[1];
    const float* target = (const float*)d_in[2];
    float* out = (float*)d_out;

    const size_t smem_bytes = 2u * LDIM * LDIM * sizeof(float2);  // 28,224 B
    cudaFuncSetAttribute(boundary_bce_fused_kernel,
                         cudaFuncAttributeMaxDynamicSharedMemorySize,
                         (int)smem_bytes);

    zero_out_kernel<<<1, 1>>>(out);

    dim3 grid(W_IMG / TILE, H_IMG / TILE, N_IMG);  // 12 x 12 x 64 = 9216 blocks
    boundary_bce_fused_kernel<<<grid, NTHREADS, smem_bytes>>>(hand, obj, target, out);
}

// round 4
// speedup vs baseline: 1.8739x; 1.2692x over previous
#include <cuda_runtime.h>

// BoundaryBCELoss: 5x clamped plus-dilation of two masks + BCE vs target, mean-reduced.
// Round 4: kill the SMEM round-trip (L1tex was 87.7%). Register-resident tiles:
//   - 48x48 tile, local domain 60 cols x 58 rows (halo-6 cols for 8B alignment, halo-5 rows)
//   - columns -> lanes (30 column-pairs, each packed u64 {hand,object})
//   - rows    -> registers (8 warps x 7-8 row bands, vertical chain in-register)
//   - horizontal neighbors via 64-bit __shfl, vertical band boundaries via a tiny
//     double-buffered SMEM exchange (2 rows/warp/iter), one __syncthreads per iter
//   - staging: coalesced LDG.64 global->registers; BCE straight from registers.

#define W_IMG 384
#define H_IMG 384
#define N_IMG 64
#define TILE 48
#define HALO_Y 5
#define HALO_X 6            // even => column pairs stay 8B-aligned in gmem
#define LDIM_Y 58           // TILE + 2*HALO_Y
#define LDIM_X 60           // TILE + 2*HALO_X
#define NP 30               // column pairs (LDIM_X / 2)
#define NW 8                // warps per CTA
#define NTHREADS 256
#define ITERS 5
#define RMAX 8              // max rows per warp band

typedef unsigned long long u64;

#define ADD_F32X2(o, a, b) \
    asm("add.rn.f32x2 %0, %1, %2;" : "=l"(o) : "l"(a), "l"(b))
#define PACK2(o, lo, hi) \
    asm("mov.b64 %0, {%1, %2};" : "=l"(o) : "f"(lo), "f"(hi))
#define UNPACK2(lo, hi, in) \
    asm("mov.b64 {%0, %1}, %2;" : "=f"(lo), "=f"(hi) : "l"(in))

__global__ void zero_out_kernel(float* out) { *out = 0.0f; }

__global__ __launch_bounds__(NTHREADS) void boundary_bce_fused_kernel(
    const float* __restrict__ hand,
    const float* __restrict__ obj,
    const float* __restrict__ target,
    float* __restrict__ out)
{
    // Boundary-row exchange: [parity][top/bot][warp][pair] -> {a,b} (16B)
    __shared__ __align__(16) u64 xbuf[2][2][NW][NP][2];
    __shared__ float red[NW];

    const int n   = blockIdx.z;
    const int y0  = blockIdx.y * TILE - HALO_Y;
    const int x0  = blockIdx.x * TILE - HALO_X;          // even
    const int tid = threadIdx.x;
    const int w   = tid >> 5;
    const int pl  = tid & 31;

    // Row bands over 58 rows: warps 0,1 -> 8 rows; warps 2..7 -> 7 rows.
    const int r_lo = 7 * w + (w < 2 ? w : 2);
    const int R    = (w < 2) ? 8 : 7;

    const int  gx       = x0 + 2 * pl;                    // even: pair {gx, gx+1} fully in or out
    const bool lane_act = (pl < NP);
    const bool col_in   = lane_act && ((unsigned)gx < W_IMG);

    const size_t img = (size_t)n * H_IMG * W_IMG;
    const float* hb = hand + img;
    const float* ob = obj + img;

    // ---- Stage band rows straight into registers (coalesced LDG.64 x2) ----
    u64 ra[RMAX], rb[RMAX];
    #pragma unroll
    for (int i = 0; i < RMAX; i++) { ra[i] = 0; rb[i] = 0; }

    #pragma unroll
    for (int i = 0; i < RMAX; i++) {
        if (i < R) {
            const int gy = y0 + r_lo + i;
            if (col_in && (unsigned)gy < H_IMG) {
                const float2 hh = *(const float2*)(hb + gy * W_IMG + gx);
                const float2 oo = *(const float2*)(ob + gy * W_IMG + gx);
                PACK2(ra[i], hh.x, oo.x);   // col 2pl   : {h, o}
                PACK2(rb[i], hh.y, oo.y);   // col 2pl+1 : {h, o}
            }
        }
    }

    // ---- 5 dilation iterations ----
    #pragma unroll 1
    for (int k = 0; k < ITERS; k++) {
        const int p = k & 1;

        if (lane_act) {
            // my top row and bottom row (old values) for neighbor warps
            u64 ba = (R == 8) ? ra[7] : ra[6];
            u64 bb = (R == 8) ? rb[7] : rb[6];
            *(ulonglong2*)&xbuf[p][0][w][pl][0] = make_ulonglong2(ra[0], rb[0]);
            *(ulonglong2*)&xbuf[p][1][w][pl][0] = make_ulonglong2(ba, bb);
        }
        __syncthreads();

        u64 pa = 0, pb = 0, na = 0, nb = 0;
        if (lane_act && w > 0) {
            ulonglong2 v = *(ulonglong2*)&xbuf[p][1][w - 1][pl][0];
            pa = v.x; pb = v.y;
        }
        if (lane_act && w < NW - 1) {
            ulonglong2 v = *(ulonglong2*)&xbuf[p][0][w + 1][pl][0];
            na = v.x; nb = v.y;
        }

        #pragma unroll
        for (int i = 0; i < RMAX; i++) {
            if (i < R) {
                const u64 ca = ra[i], cb = rb[i];
                u64 xa = na, xb = nb;
                if (i + 1 < RMAX) {
                    if (i + 1 < R) { xa = ra[i + 1]; xb = rb[i + 1]; }
                }
                const u64 lf = __shfl_up_sync(0xffffffffu, cb, 1);   // col 2pl-1
                const u64 rt = __shfl_down_sync(0xffffffffu, ca, 1); // col 2pl+2

                // out(2pl)   = lf + ca + cb + up_a + dn_a
                // out(2pl+1) = ca + cb + rt + up_b + dn_b   (t = ca+cb shared)
                u64 t, s0, s1;
                ADD_F32X2(t, ca, cb);
                ADD_F32X2(s0, t, lf);
                ADD_F32X2(s0, s0, pa);
                ADD_F32X2(s0, s0, xa);
                ADD_F32X2(s1, t, rt);
                ADD_F32X2(s1, s1, pb);
                ADD_F32X2(s1, s1, xb);

                float a0, a1, b0, b1;
                UNPACK2(a0, a1, s0);
                UNPACK2(b0, b1, s1);
                a0 = fminf(a0, 1.0f); a1 = fminf(a1, 1.0f);
                b0 = fminf(b0, 1.0f); b1 = fminf(b1, 1.0f);

                // Re-zero out-of-image cells: reference zero-pads EVERY conv.
                const bool rin = (unsigned)(y0 + r_lo + i) < H_IMG;
                const bool in  = rin && col_in;
                a0 = in ? a0 : 0.0f;  a1 = in ? a1 : 0.0f;
                b0 = in ? b0 : 0.0f;  b1 = in ? b1 : 0.0f;

                pa = ca; pb = cb;                    // old row becomes "up" for next row
                PACK2(ra[i], a0, a1);
                PACK2(rb[i], b0, b1);
            }
        }
        // single sync per iter is safe: next iter stores go to the other parity slot
    }

    // ---- BCE straight from registers ----
    // inner cols: local [6,54) <=> lanes 3..26 (full pairs); inner rows: local [5,53)
    float lsum = 0.0f;
    if (pl >= 3 && pl <= 26) {
        const float* tb = target + img;
        #pragma unroll
        for (int i = 0; i < RMAX; i++) {
            if (i < R) {
                const int rl = r_lo + i;
                if (rl >= HALO_Y && rl < HALO_Y + TILE) {
                    const int gy = y0 + rl;
                    const float2 t2 = *(const float2*)(tb + gy * W_IMG + gx);
                    float h0, o0, h1, o1;
                    UNPACK2(h0, o0, ra[i]);
                    UNPACK2(h1, o1, rb[i]);
                    const float p0 = h0 * o0;
                    const float p1 = h1 * o1;
                    float c0, c1;
                    if (p0 >= 1.0f) c0 = -100.0f * (1.0f - t2.x);
                    else {
                        float lp  = fmaxf(logf(p0), -100.0f);
                        float l1p = fmaxf(logf(1.0f - p0), -100.0f);
                        c0 = t2.x * lp + (1.0f - t2.x) * l1p;
                    }
                    if (p1 >= 1.0f) c1 = -100.0f * (1.0f - t2.y);
                    else {
                        float lp  = fmaxf(logf(p1), -100.0f);
                        float l1p = fmaxf(logf(1.0f - p1), -100.0f);
                        c1 = t2.y * lp + (1.0f - t2.y) * l1p;
                    }
                    lsum += c0 + c1;
                }
            }
        }
    }

    // ---- Reduction ----
    #pragma unroll
    for (int off = 16; off > 0; off >>= 1)
        lsum += __shfl_down_sync(0xffffffffu, lsum, off);

    if (pl == 0) red[w] = lsum;
    __syncthreads();

    if (tid < NW) {
        float v = red[tid];
        #pragma unroll
        for (int off = NW / 2; off > 0; off >>= 1)
            v += __shfl_down_sync((1u << NW) - 1u, v, off);
        if (tid == 0) {
            const float inv_total = 1.0f / ((float)N_IMG * H_IMG * W_IMG);
            atomicAdd(out, -v * inv_total);
        }
    }
}

extern "C" void kernel_launch(void* const* d_in, const int* in_sizes, int n_in,
                              void* d_out, int out_size)
{
    const float* hand   = (const float*)d_in[0];
    const float* obj    = (const float*)d_in[1];
    const float* target = (const float*)d_in[2];
    float* out = (float*)d_out;

    zero_out_kernel<<<1, 1>>>(out);

    dim3 grid(W_IMG / TILE, H_IMG / TILE, N_IMG);   // 8 x 8 x 64 = 4096 blocks
    boundary_bce_fused_kernel<<<grid, NTHREADS>>>(hand, obj, target, out);
}